// round 1
// baseline (speedup 1.0000x reference)
#include <cuda_runtime.h>
#include <math_constants.h>
#include <cstdint>

#define T_LEN   4096
#define D_MODEL 1024
#define NHEAD   8
#define HDIM    128
#define ATTN_SCALE 0.12f

// ---------------- scratch (static device globals; no allocation) -------------
__device__ float g_qkv[(size_t)T_LEN * 3 * D_MODEL];        // [T][3][H*Hd]
__device__ float g_q[(size_t)NHEAD * T_LEN * HDIM];         // [H][T][Hd]
__device__ float g_k[(size_t)NHEAD * T_LEN * HDIM];
__device__ float g_v[(size_t)NHEAD * T_LEN * HDIM];
__device__ float g_y[(size_t)T_LEN * D_MODEL];              // [T][H*Hd]

// ---------------- generic fp32 NT GEMM: C[M,N] = A[M,K] * B[N,K]^T ----------
// BM=BN=128, BK=8, 256 threads, 8x8 micro-tile per thread.
__global__ __launch_bounds__(256) void gemm_nt(const float* __restrict__ A,
                                               const float* __restrict__ B,
                                               float* __restrict__ C,
                                               int M, int N, int K) {
    __shared__ float As[8][128];
    __shared__ float Bs[8][128];
    const int bm = blockIdx.y * 128;
    const int bn = blockIdx.x * 128;
    const int tid = threadIdx.x;
    const int tx = tid & 15;        // 0..15
    const int ty = tid >> 4;        // 0..15
    const int lr = tid >> 1;        // 0..127 (load row)
    const int lc = (tid & 1) * 4;   // 0 or 4 (load col)

    float acc[8][8];
#pragma unroll
    for (int i = 0; i < 8; i++)
#pragma unroll
        for (int j = 0; j < 8; j++) acc[i][j] = 0.f;

    for (int k0 = 0; k0 < K; k0 += 8) {
        float4 av = *(const float4*)(A + (size_t)(bm + lr) * K + k0 + lc);
        float4 bv = *(const float4*)(B + (size_t)(bn + lr) * K + k0 + lc);
        __syncthreads();
        As[lc + 0][lr] = av.x; As[lc + 1][lr] = av.y;
        As[lc + 2][lr] = av.z; As[lc + 3][lr] = av.w;
        Bs[lc + 0][lr] = bv.x; Bs[lc + 1][lr] = bv.y;
        Bs[lc + 2][lr] = bv.z; Bs[lc + 3][lr] = bv.w;
        __syncthreads();
#pragma unroll
        for (int kk = 0; kk < 8; kk++) {
            float ra[8], rb[8];
#pragma unroll
            for (int i = 0; i < 8; i++) ra[i] = As[kk][ty * 8 + i];
#pragma unroll
            for (int j = 0; j < 8; j++) rb[j] = Bs[kk][tx * 8 + j];
#pragma unroll
            for (int i = 0; i < 8; i++)
#pragma unroll
                for (int j = 0; j < 8; j++) acc[i][j] = fmaf(ra[i], rb[j], acc[i][j]);
        }
    }
#pragma unroll
    for (int i = 0; i < 8; i++) {
        float* cp = C + (size_t)(bm + ty * 8 + i) * N + bn + tx * 8;
#pragma unroll
        for (int j = 0; j < 8; j++) cp[j] = acc[i][j];
    }
}

// ---------------- RMSNorm + rotary (q,k) + V blend --------------------------
// grid (T, H), 128 threads; thread d handles dim d of head h at token t.
__global__ __launch_bounds__(128) void qkv_post(const float* __restrict__ qkv,
                                                const float* __restrict__ ve,
                                                const float* __restrict__ lambdas,
                                                float* __restrict__ Q,
                                                float* __restrict__ K,
                                                float* __restrict__ V) {
    const int t = blockIdx.x, h = blockIdx.y, d = threadIdx.x;
    const int lane = d & 31, wid = d >> 5;
    const float* base = qkv + (size_t)t * (3 * D_MODEL) + h * HDIM;

    float qv = base[d];
    float kv = base[D_MODEL + d];
    float vv = base[2 * D_MODEL + d];

    // RMS over the 128 dims for q and k
    float s1 = qv * qv, s2 = kv * kv;
#pragma unroll
    for (int o = 16; o; o >>= 1) {
        s1 += __shfl_xor_sync(0xffffffffu, s1, o);
        s2 += __shfl_xor_sync(0xffffffffu, s2, o);
    }
    __shared__ float w1[4], w2[4];
    if (lane == 0) { w1[wid] = s1; w2[wid] = s2; }
    __syncthreads();
    float sq = w1[0] + w1[1] + w1[2] + w1[3];
    float sk = w2[0] + w2[1] + w2[2] + w2[3];
    const float eps = 1.1920929e-7f;
    float rq = rsqrtf(sq * (1.0f / 128.0f) + eps);
    float rk = rsqrtf(sk * (1.0f / 128.0f) + eps);
    float qn = qv * rq, kn = kv * rk;

    __shared__ float qs[128], ks[128];
    qs[d] = qn; ks[d] = kn;
    __syncthreads();

    // rotary tables: quarter=32 real frequencies, rest zero
    int j = d & 63;
    float ang = (j < 32) ? powf(1.0f / 1024.0f, (float)j / 31.0f) : 0.0f;
    float theta = (float)t * ang;
    float c, s;
    sincosf(theta, &s, &c);

    float qo, ko;
    if (d < 64) {
        qo =  qs[d] * c + qs[d + 64] * s;
        ko =  ks[d] * c + ks[d + 64] * s;
    } else {
        qo = -qs[d - 64] * s + qs[d] * c;
        ko = -ks[d - 64] * s + ks[d] * c;
    }

    float l0 = lambdas[0], l1 = lambdas[1];
    float vo = l0 * vv + l1 * ve[(size_t)t * D_MODEL + h * HDIM + d];

    size_t o = ((size_t)h * T_LEN + t) * HDIM + d;
    Q[o] = qo; K[o] = ko; V[o] = vo;
}

// ---------------- causal flash attention (fp32) ------------------------------
// grid (T/32, H), 256 threads (8 warps). Warp w owns queries t0 + w + 8*qi.
__global__ __launch_bounds__(256) void flash_attn(const float* __restrict__ Q,
                                                  const float* __restrict__ K,
                                                  const float* __restrict__ V,
                                                  float* __restrict__ Y) {
    const int h  = blockIdx.y;
    const int t0 = blockIdx.x * 32;
    const int tid = threadIdx.x;
    const int w = tid >> 5, lane = tid & 31;

    __shared__ float Ks[32][128];
    __shared__ float Vs[32][128];

    const float* Qh = Q + (size_t)h * T_LEN * HDIM;
    const float* Kh = K + (size_t)h * T_LEN * HDIM;
    const float* Vh = V + (size_t)h * T_LEN * HDIM;

    int   tq[4];
    float qv[4][4], acc[4][4], m[4], l[4];
#pragma unroll
    for (int qi = 0; qi < 4; qi++) {
        tq[qi] = t0 + w + 8 * qi;
        m[qi] = -CUDART_INF_F; l[qi] = 0.f;
#pragma unroll
        for (int i = 0; i < 4; i++) {
            qv[qi][i] = Qh[(size_t)tq[qi] * HDIM + lane + 32 * i];
            acc[qi][i] = 0.f;
        }
    }

    const int tmax = t0 + 31;
    for (int s0 = 0; s0 <= tmax; s0 += 32) {
        __syncthreads();
        const float4* gk = (const float4*)(Kh + (size_t)s0 * HDIM);
        const float4* gv = (const float4*)(Vh + (size_t)s0 * HDIM);
        float4* sk = (float4*)&Ks[0][0];
        float4* sv = (float4*)&Vs[0][0];
#pragma unroll
        for (int r = 0; r < 4; r++) {
            sk[tid + 256 * r] = gk[tid + 256 * r];
            sv[tid + 256 * r] = gv[tid + 256 * r];
        }
        __syncthreads();

        float tsc[4];
#pragma unroll
        for (int qi = 0; qi < 4; qi++) tsc[qi] = -CUDART_INF_F;

        for (int j = 0; j < 32; j++) {
            float kx0 = Ks[j][lane], kx1 = Ks[j][lane + 32];
            float kx2 = Ks[j][lane + 64], kx3 = Ks[j][lane + 96];
            float sc[4];
#pragma unroll
            for (int qi = 0; qi < 4; qi++)
                sc[qi] = qv[qi][0] * kx0 + qv[qi][1] * kx1 +
                         qv[qi][2] * kx2 + qv[qi][3] * kx3;
#pragma unroll
            for (int o = 16; o; o >>= 1) {
#pragma unroll
                for (int qi = 0; qi < 4; qi++)
                    sc[qi] += __shfl_xor_sync(0xffffffffu, sc[qi], o);
            }
            int s = s0 + j;
            if (lane == j) {
#pragma unroll
                for (int qi = 0; qi < 4; qi++)
                    tsc[qi] = (s <= tq[qi]) ? sc[qi] * ATTN_SCALE : -CUDART_INF_F;
            }
        }

        float p[4];
#pragma unroll
        for (int qi = 0; qi < 4; qi++) {
            float tm = tsc[qi];
#pragma unroll
            for (int o = 16; o; o >>= 1)
                tm = fmaxf(tm, __shfl_xor_sync(0xffffffffu, tm, o));
            if (tm == -CUDART_INF_F) { p[qi] = 0.f; continue; }
            float mnew = fmaxf(m[qi], tm);
            float scl = expf(m[qi] - mnew);      // m=-inf -> 0
            p[qi] = expf(tsc[qi] - mnew);        // lane j holds p_j
            float ps = p[qi];
#pragma unroll
            for (int o = 16; o; o >>= 1)
                ps += __shfl_xor_sync(0xffffffffu, ps, o);
            l[qi] = l[qi] * scl + ps;
#pragma unroll
            for (int i = 0; i < 4; i++) acc[qi][i] *= scl;
            m[qi] = mnew;
        }

        for (int j = 0; j < 32; j++) {
            float vx0 = Vs[j][lane], vx1 = Vs[j][lane + 32];
            float vx2 = Vs[j][lane + 64], vx3 = Vs[j][lane + 96];
#pragma unroll
            for (int qi = 0; qi < 4; qi++) {
                float pj = __shfl_sync(0xffffffffu, p[qi], j);
                acc[qi][0] = fmaf(pj, vx0, acc[qi][0]);
                acc[qi][1] = fmaf(pj, vx1, acc[qi][1]);
                acc[qi][2] = fmaf(pj, vx2, acc[qi][2]);
                acc[qi][3] = fmaf(pj, vx3, acc[qi][3]);
            }
        }
    }

#pragma unroll
    for (int qi = 0; qi < 4; qi++) {
        float inv = 1.0f / l[qi];
#pragma unroll
        for (int i = 0; i < 4; i++)
            Y[(size_t)tq[qi] * D_MODEL + h * HDIM + lane + 32 * i] = acc[qi][i] * inv;
    }
}

// ---------------- launch ------------------------------------------------------
extern "C" void kernel_launch(void* const* d_in, const int* in_sizes, int n_in,
                              void* d_out, int out_size) {
    const float* x        = (const float*)d_in[0];  // [1,4096,1024]
    const float* ve       = (const float*)d_in[1];  // [1,4096,1024]
    const float* qkv_w    = (const float*)d_in[2];  // [3,1024,1024]
    const float* lambdas  = (const float*)d_in[3];  // [2]
    const float* c_proj_w = (const float*)d_in[4];  // [1024,1024]
    float* out = (float*)d_out;                     // [1,4096,1024]

    float *p_qkv, *p_q, *p_k, *p_v, *p_y;
    cudaGetSymbolAddress((void**)&p_qkv, g_qkv);
    cudaGetSymbolAddress((void**)&p_q, g_q);
    cudaGetSymbolAddress((void**)&p_k, g_k);
    cudaGetSymbolAddress((void**)&p_v, g_v);
    cudaGetSymbolAddress((void**)&p_y, g_y);

    // 1) QKV projection: [4096,1024] x [3072,1024]^T -> [4096,3072]
    gemm_nt<<<dim3(3 * D_MODEL / 128, T_LEN / 128), 256>>>(
        x, qkv_w, p_qkv, T_LEN, 3 * D_MODEL, D_MODEL);

    // 2) RMSNorm + rotary + V blend
    qkv_post<<<dim3(T_LEN, NHEAD), 128>>>(p_qkv, ve, lambdas, p_q, p_k, p_v);

    // 3) causal flash attention -> y [4096, 1024]
    flash_attn<<<dim3(T_LEN / 32, NHEAD), 256>>>(p_q, p_k, p_v, p_y);

    // 4) output projection: [4096,1024] x [1024,1024]^T -> [4096,1024]
    gemm_nt<<<dim3(D_MODEL / 128, T_LEN / 128), 256>>>(
        p_y, c_proj_w, out, T_LEN, D_MODEL, D_MODEL);
}

// round 2
// speedup vs baseline: 1.5707x; 1.5707x over previous
#include <cuda_runtime.h>
#include <math_constants.h>
#include <cstdint>

#define T_LEN   4096
#define D_MODEL 1024
#define NHEAD   8
#define HDIM    128
#define ATTN_SCALE 0.12f

typedef unsigned long long ull;

// ---------------- f32x2 packed-math helpers (sm_100+) ------------------------
__device__ __forceinline__ ull pack2(float a, float b) {
    ull r; asm("mov.b64 %0, {%1,%2};" : "=l"(r) : "f"(a), "f"(b)); return r;
}
__device__ __forceinline__ ull dup2(float a) { return pack2(a, a); }
__device__ __forceinline__ void fma2(ull& d, ull a, ull b) {
    asm("fma.rn.f32x2 %0, %1, %2, %0;" : "+l"(d) : "l"(a), "l"(b));
}
__device__ __forceinline__ void mul2(ull& d, ull a) {
    asm("mul.rn.f32x2 %0, %0, %1;" : "+l"(d) : "l"(a));
}
__device__ __forceinline__ float2 unpk2(ull v) {
    float2 f; asm("mov.b64 {%0,%1}, %2;" : "=f"(f.x), "=f"(f.y) : "l"(v)); return f;
}

// ---------------- scratch (static device globals; no allocation) -------------
__device__ float g_qkv[(size_t)T_LEN * 3 * D_MODEL];
__device__ float g_q[(size_t)NHEAD * T_LEN * HDIM];
__device__ float g_k[(size_t)NHEAD * T_LEN * HDIM];
__device__ float g_v[(size_t)NHEAD * T_LEN * HDIM];
__device__ float g_y[(size_t)T_LEN * D_MODEL];

// ---------------- fp32 NT GEMM with f32x2: C[M,N] = A[M,K] * B[N,K]^T --------
__global__ __launch_bounds__(256) void gemm_nt(const float* __restrict__ A,
                                               const float* __restrict__ B,
                                               float* __restrict__ C,
                                               int M, int N, int K) {
    __shared__ float As[8][128];
    __shared__ float Bs[8][128];
    const int bm = blockIdx.y * 128;
    const int bn = blockIdx.x * 128;
    const int tid = threadIdx.x;
    const int tx = tid & 15;
    const int ty = tid >> 4;
    const int lr = tid >> 1;
    const int lc = (tid & 1) * 4;

    ull acc2[8][4];
#pragma unroll
    for (int i = 0; i < 8; i++)
#pragma unroll
        for (int j = 0; j < 4; j++) acc2[i][j] = 0ull;

    for (int k0 = 0; k0 < K; k0 += 8) {
        float4 av = *(const float4*)(A + (size_t)(bm + lr) * K + k0 + lc);
        float4 bv = *(const float4*)(B + (size_t)(bn + lr) * K + k0 + lc);
        __syncthreads();
        As[lc + 0][lr] = av.x; As[lc + 1][lr] = av.y;
        As[lc + 2][lr] = av.z; As[lc + 3][lr] = av.w;
        Bs[lc + 0][lr] = bv.x; Bs[lc + 1][lr] = bv.y;
        Bs[lc + 2][lr] = bv.z; Bs[lc + 3][lr] = bv.w;
        __syncthreads();
#pragma unroll
        for (int kk = 0; kk < 8; kk++) {
            float4 a0 = *(const float4*)&As[kk][ty * 8];
            float4 a1 = *(const float4*)&As[kk][ty * 8 + 4];
            ulonglong2 b01 = *(const ulonglong2*)&Bs[kk][tx * 8];
            ulonglong2 b23 = *(const ulonglong2*)&Bs[kk][tx * 8 + 4];
            ull ra[8];
            ra[0] = dup2(a0.x); ra[1] = dup2(a0.y); ra[2] = dup2(a0.z); ra[3] = dup2(a0.w);
            ra[4] = dup2(a1.x); ra[5] = dup2(a1.y); ra[6] = dup2(a1.z); ra[7] = dup2(a1.w);
#pragma unroll
            for (int i = 0; i < 8; i++) {
                fma2(acc2[i][0], ra[i], b01.x);
                fma2(acc2[i][1], ra[i], b01.y);
                fma2(acc2[i][2], ra[i], b23.x);
                fma2(acc2[i][3], ra[i], b23.y);
            }
        }
    }
#pragma unroll
    for (int i = 0; i < 8; i++) {
        float* cp = C + (size_t)(bm + ty * 8 + i) * N + bn + tx * 8;
        ulonglong2 s0; s0.x = acc2[i][0]; s0.y = acc2[i][1];
        ulonglong2 s1; s1.x = acc2[i][2]; s1.y = acc2[i][3];
        *(ulonglong2*)(cp)     = s0;
        *(ulonglong2*)(cp + 4) = s1;
    }
}

// ---------------- RMSNorm + rotary (q,k) + V blend --------------------------
__global__ __launch_bounds__(128) void qkv_post(const float* __restrict__ qkv,
                                                const float* __restrict__ ve,
                                                const float* __restrict__ lambdas,
                                                float* __restrict__ Q,
                                                float* __restrict__ K,
                                                float* __restrict__ V) {
    const int t = blockIdx.x, h = blockIdx.y, d = threadIdx.x;
    const int lane = d & 31, wid = d >> 5;
    const float* base = qkv + (size_t)t * (3 * D_MODEL) + h * HDIM;

    float qv = base[d];
    float kv = base[D_MODEL + d];
    float vv = base[2 * D_MODEL + d];

    float s1 = qv * qv, s2 = kv * kv;
#pragma unroll
    for (int o = 16; o; o >>= 1) {
        s1 += __shfl_xor_sync(0xffffffffu, s1, o);
        s2 += __shfl_xor_sync(0xffffffffu, s2, o);
    }
    __shared__ float w1[4], w2[4];
    if (lane == 0) { w1[wid] = s1; w2[wid] = s2; }
    __syncthreads();
    float sq = w1[0] + w1[1] + w1[2] + w1[3];
    float sk = w2[0] + w2[1] + w2[2] + w2[3];
    const float eps = 1.1920929e-7f;
    float rq = rsqrtf(sq * (1.0f / 128.0f) + eps);
    float rk = rsqrtf(sk * (1.0f / 128.0f) + eps);
    float qn = qv * rq, kn = kv * rk;

    __shared__ float qs[128], ks[128];
    qs[d] = qn; ks[d] = kn;
    __syncthreads();

    int j = d & 63;
    float ang = (j < 32) ? powf(1.0f / 1024.0f, (float)j / 31.0f) : 0.0f;
    float theta = (float)t * ang;
    float c, s;
    sincosf(theta, &s, &c);

    float qo, ko;
    if (d < 64) {
        qo =  qs[d] * c + qs[d + 64] * s;
        ko =  ks[d] * c + ks[d + 64] * s;
    } else {
        qo = -qs[d - 64] * s + qs[d] * c;
        ko = -ks[d - 64] * s + ks[d] * c;
    }

    float l0 = lambdas[0], l1 = lambdas[1];
    float vo = l0 * vv + l1 * ve[(size_t)t * D_MODEL + h * HDIM + d];

    size_t o = ((size_t)h * T_LEN + t) * HDIM + d;
    Q[o] = qo; K[o] = ko; V[o] = vo;
}

// ---------------- GEMM-style causal flash attention (fp32, f32x2) ------------
// grid (T/64, H), 256 threads. Block handles 64 queries, loops 64-key tiles.
// Smem (dynamic): Qs[128][64] (k-major), Ks[128][64] (k-major),
//                 Vs[64][128], Ps[64][68], Ms[64], Ls[64].
#define PS_STRIDE 68
__global__ __launch_bounds__(256) void flash_attn(const float* __restrict__ Q,
                                                  const float* __restrict__ K,
                                                  const float* __restrict__ V,
                                                  float* __restrict__ Y) {
    extern __shared__ float sm[];
    float* Qs = sm;                       // 128*64
    float* Ks = Qs + 128 * 64;            // 128*64
    float* Vs = Ks + 128 * 64;            // 64*128
    float* Ps = Vs + 64 * 128;            // 64*PS_STRIDE
    float* Ms = Ps + 64 * PS_STRIDE;      // 64
    float* Ls = Ms + 64;                  // 64

    const int h = blockIdx.y;
    const int qbase = blockIdx.x * 64;
    const int tid = threadIdx.x;
    const int tx = tid & 15;   // score cols group (4), out cols group (8)
    const int ty = tid >> 4;   // q-row group of 4 (shared by both phases)

    const float* Qh = Q + (size_t)h * T_LEN * HDIM;
    const float* Kh = K + (size_t)h * T_LEN * HDIM;
    const float* Vh = V + (size_t)h * T_LEN * HDIM;

    // init row state
    if (tid < 64) { Ms[tid] = -1e30f; Ls[tid] = 0.f; }

    // load Q tile transposed: Qs[d][tloc]
#pragma unroll
    for (int r = 0; r < 8; r++) {
        int e = tid + 256 * r;           // 0..2047
        int tloc = e & 63;
        int d0 = (e >> 6) * 4;
        float4 qv = *(const float4*)(Qh + (size_t)(qbase + tloc) * HDIM + d0);
        Qs[(d0 + 0) * 64 + tloc] = qv.x;
        Qs[(d0 + 1) * 64 + tloc] = qv.y;
        Qs[(d0 + 2) * 64 + tloc] = qv.z;
        Qs[(d0 + 3) * 64 + tloc] = qv.w;
    }

    // per-thread output accumulators: rows ty*4+i, cols tx*8..tx*8+7 (4 ull each)
    ull acc2[4][4];
#pragma unroll
    for (int i = 0; i < 4; i++)
#pragma unroll
        for (int j = 0; j < 4; j++) acc2[i][j] = 0ull;

    for (int s0 = 0; s0 <= qbase; s0 += 64) {
        __syncthreads();   // protect Ks/Vs/Ps from previous iteration readers

        // load K tile transposed Ks[d][sloc], V tile natural Vs[sloc][d]
#pragma unroll
        for (int r = 0; r < 8; r++) {
            int e = tid + 256 * r;
            int sloc = e & 63;
            int d0 = (e >> 6) * 4;
            float4 kv = *(const float4*)(Kh + (size_t)(s0 + sloc) * HDIM + d0);
            Ks[(d0 + 0) * 64 + sloc] = kv.x;
            Ks[(d0 + 1) * 64 + sloc] = kv.y;
            Ks[(d0 + 2) * 64 + sloc] = kv.z;
            Ks[(d0 + 3) * 64 + sloc] = kv.w;
            int sv = e >> 5;
            int dv = (e & 31) * 4;
            *(float4*)&Vs[sv * 128 + dv] =
                *(const float4*)(Vh + (size_t)(s0 + sv) * HDIM + dv);
        }
        __syncthreads();

        // ---- phase 1: S = Q K^T  (rows ty*4+i, cols tx*4+j) ----
        ull s2[4][2];
#pragma unroll
        for (int i = 0; i < 4; i++) { s2[i][0] = 0ull; s2[i][1] = 0ull; }

#pragma unroll 4
        for (int kk = 0; kk < 128; kk++) {
            float4 qa = *(const float4*)&Qs[kk * 64 + ty * 4];
            ulonglong2 kb = *(const ulonglong2*)&Ks[kk * 64 + tx * 4];
            ull ra0 = dup2(qa.x), ra1 = dup2(qa.y), ra2 = dup2(qa.z), ra3 = dup2(qa.w);
            fma2(s2[0][0], ra0, kb.x); fma2(s2[0][1], ra0, kb.y);
            fma2(s2[1][0], ra1, kb.x); fma2(s2[1][1], ra1, kb.y);
            fma2(s2[2][0], ra2, kb.x); fma2(s2[2][1], ra2, kb.y);
            fma2(s2[3][0], ra3, kb.x); fma2(s2[3][1], ra3, kb.y);
        }

        // ---- phase 2: masked online softmax ----
        float p[4][4], rscale[4];
#pragma unroll
        for (int i = 0; i < 4; i++) {
            int q = qbase + ty * 4 + i;
            float2 c0 = unpk2(s2[i][0]);
            float2 c1 = unpk2(s2[i][1]);
            float sc[4] = { c0.x, c0.y, c1.x, c1.y };
#pragma unroll
            for (int j = 0; j < 4; j++) {
                int s = s0 + tx * 4 + j;
                sc[j] = (s <= q) ? sc[j] * ATTN_SCALE : -1e30f;
            }
            float rmax = fmaxf(fmaxf(sc[0], sc[1]), fmaxf(sc[2], sc[3]));
#pragma unroll
            for (int o = 8; o; o >>= 1)
                rmax = fmaxf(rmax, __shfl_xor_sync(0xffffffffu, rmax, o));
            float mold = Ms[ty * 4 + i];
            float mnew = fmaxf(mold, rmax);
            rscale[i] = __expf(mold - mnew);
            float rsum = 0.f;
#pragma unroll
            for (int j = 0; j < 4; j++) {
                p[i][j] = __expf(sc[j] - mnew);
                rsum += p[i][j];
            }
#pragma unroll
            for (int o = 8; o; o >>= 1)
                rsum += __shfl_xor_sync(0xffffffffu, rsum, o);
            // stash updates in registers; commit after barrier (tx==0)
            sc[0] = mnew; sc[1] = rsum;   // reuse
            s2[i][0] = pack2(mnew, rsum); // carry to post-barrier commit
        }
        __syncthreads();   // all Ms reads done
        if (tx == 0) {
#pragma unroll
            for (int i = 0; i < 4; i++) {
                float2 mr = unpk2(s2[i][0]);
                int row = ty * 4 + i;
                Ms[row] = mr.x;
                Ls[row] = Ls[row] * rscale[i] + mr.y;
            }
        }
        // write P transposed: Ps[scol][qrow]
#pragma unroll
        for (int j = 0; j < 4; j++) {
#pragma unroll
            for (int i = 0; i < 4; i++)
                Ps[(tx * 4 + j) * PS_STRIDE + ty * 4 + i] = p[i][j];
        }
        // rescale accumulators
#pragma unroll
        for (int i = 0; i < 4; i++) {
            ull rs = dup2(rscale[i]);
            mul2(acc2[i][0], rs); mul2(acc2[i][1], rs);
            mul2(acc2[i][2], rs); mul2(acc2[i][3], rs);
        }
        __syncthreads();   // Ps/Ls/Ms committed

        // ---- phase 3: acc += P @ V  (rows ty*4+i, cols tx*8..+7) ----
#pragma unroll 4
        for (int kk = 0; kk < 64; kk++) {
            float4 pa = *(const float4*)&Ps[kk * PS_STRIDE + ty * 4];
            ulonglong2 v01 = *(const ulonglong2*)&Vs[kk * 128 + tx * 8];
            ulonglong2 v23 = *(const ulonglong2*)&Vs[kk * 128 + tx * 8 + 4];
            ull ra0 = dup2(pa.x), ra1 = dup2(pa.y), ra2 = dup2(pa.z), ra3 = dup2(pa.w);
            fma2(acc2[0][0], ra0, v01.x); fma2(acc2[0][1], ra0, v01.y);
            fma2(acc2[0][2], ra0, v23.x); fma2(acc2[0][3], ra0, v23.y);
            fma2(acc2[1][0], ra1, v01.x); fma2(acc2[1][1], ra1, v01.y);
            fma2(acc2[1][2], ra1, v23.x); fma2(acc2[1][3], ra1, v23.y);
            fma2(acc2[2][0], ra2, v01.x); fma2(acc2[2][1], ra2, v01.y);
            fma2(acc2[2][2], ra2, v23.x); fma2(acc2[2][3], ra2, v23.y);
            fma2(acc2[3][0], ra3, v01.x); fma2(acc2[3][1], ra3, v01.y);
            fma2(acc2[3][2], ra3, v23.x); fma2(acc2[3][3], ra3, v23.y);
        }
    }

    // ---- epilogue: normalize and store ----
#pragma unroll
    for (int i = 0; i < 4; i++) {
        float inv = 1.0f / Ls[ty * 4 + i];
        ull iv = dup2(inv);
        mul2(acc2[i][0], iv); mul2(acc2[i][1], iv);
        mul2(acc2[i][2], iv); mul2(acc2[i][3], iv);
        float* yp = Y + (size_t)(qbase + ty * 4 + i) * D_MODEL + h * HDIM + tx * 8;
        ulonglong2 o0; o0.x = acc2[i][0]; o0.y = acc2[i][1];
        ulonglong2 o1; o1.x = acc2[i][2]; o1.y = acc2[i][3];
        *(ulonglong2*)(yp)     = o0;
        *(ulonglong2*)(yp + 4) = o1;
    }
}

// ---------------- launch ------------------------------------------------------
extern "C" void kernel_launch(void* const* d_in, const int* in_sizes, int n_in,
                              void* d_out, int out_size) {
    const float* x        = (const float*)d_in[0];
    const float* ve       = (const float*)d_in[1];
    const float* qkv_w    = (const float*)d_in[2];
    const float* lambdas  = (const float*)d_in[3];
    const float* c_proj_w = (const float*)d_in[4];
    float* out = (float*)d_out;

    float *p_qkv, *p_q, *p_k, *p_v, *p_y;
    cudaGetSymbolAddress((void**)&p_qkv, g_qkv);
    cudaGetSymbolAddress((void**)&p_q, g_q);
    cudaGetSymbolAddress((void**)&p_k, g_k);
    cudaGetSymbolAddress((void**)&p_v, g_v);
    cudaGetSymbolAddress((void**)&p_y, g_y);

    const int attn_smem = (128 * 64 + 128 * 64 + 64 * 128 + 64 * PS_STRIDE + 128)
                          * (int)sizeof(float);
    static bool attr_set = false;
    if (!attr_set) {
        cudaFuncSetAttribute(flash_attn, cudaFuncAttributeMaxDynamicSharedMemorySize,
                             attn_smem);
        attr_set = true;
    }

    gemm_nt<<<dim3(3 * D_MODEL / 128, T_LEN / 128), 256>>>(
        x, qkv_w, p_qkv, T_LEN, 3 * D_MODEL, D_MODEL);

    qkv_post<<<dim3(T_LEN, NHEAD), 128>>>(p_qkv, ve, lambdas, p_q, p_k, p_v);

    flash_attn<<<dim3(T_LEN / 64, NHEAD), 256, attn_smem>>>(p_q, p_k, p_v, p_y);

    gemm_nt<<<dim3(D_MODEL / 128, T_LEN / 128), 256>>>(
        p_y, c_proj_w, out, T_LEN, D_MODEL, D_MODEL);
}

// round 3
// speedup vs baseline: 4.0947x; 2.6070x over previous
#include <cuda_runtime.h>
#include <cstdint>

#define T_LEN   4096
#define D_MODEL 1024
#define NHEAD   8
#define HDIM    128
#define ATTN_SCALE 0.12f

// ---------------- tf32 mma helpers ------------------------------------------
__device__ __forceinline__ unsigned f2tf(float f) {
    unsigned u; asm("cvt.rna.tf32.f32 %0, %1;" : "=r"(u) : "f"(f)); return u;
}
__device__ __forceinline__ void mma_tf32(float* d,
    unsigned a0, unsigned a1, unsigned a2, unsigned a3,
    unsigned b0, unsigned b1) {
    asm volatile("mma.sync.aligned.m16n8k8.row.col.f32.tf32.tf32.f32 "
        "{%0,%1,%2,%3},{%4,%5,%6,%7},{%8,%9},{%0,%1,%2,%3};"
        : "+f"(d[0]), "+f"(d[1]), "+f"(d[2]), "+f"(d[3])
        : "r"(a0), "r"(a1), "r"(a2), "r"(a3), "r"(b0), "r"(b1));
}
// interleave within 8-groups: col pairs (c, c+4) become adjacent -> lds.64 frags
__device__ __forceinline__ int icol8(int k) {
    return (k & ~7) | ((k & 3) << 1) | ((k >> 2) & 1);
}
// FMA-only expf (avoids MUFU wall); ~1e-4 rel err, exp(-huge)->0
__device__ __forceinline__ float fexp(float x) {
    float t = x * 1.4426950408889634f;
    float f = floorf(t);
    float r = t - f;
    float p = 1.3400000e-3f;
    p = fmaf(p, r, 9.6770508e-3f);
    p = fmaf(p, r, 5.5503310e-2f);
    p = fmaf(p, r, 2.4022652e-1f);
    p = fmaf(p, r, 6.9314718e-1f);
    p = fmaf(p, r, 1.0f);
    int e = (int)f;
    e = max(e, -127);
    float s = __int_as_float((unsigned)(e + 127) << 23);
    return p * s;
}

// ---------------- scratch ----------------------------------------------------
__device__ float g_qkv[(size_t)T_LEN * 3 * D_MODEL];
__device__ float g_q[(size_t)NHEAD * T_LEN * HDIM];   // tf32 bits, d interleaved, *ATTN_SCALE
__device__ float g_k[(size_t)NHEAD * T_LEN * HDIM];   // tf32 bits, d interleaved
__device__ float g_v[(size_t)NHEAD * T_LEN * HDIM];   // tf32 bits, natural d
__device__ float g_y[(size_t)T_LEN * D_MODEL];

// ---------------- tf32 NT GEMM: C[M,N] = A[M,K] * B[N,K]^T -------------------
// 256 thr, 8 warps (4 M x 2 N), warp tile 32x64, BK=32.
__global__ __launch_bounds__(256) void gemm_nt_tf32(const float* __restrict__ A,
                                                    const float* __restrict__ B,
                                                    float* __restrict__ C,
                                                    int M, int N, int K) {
    __shared__ unsigned As[128 * 36];
    __shared__ unsigned Bs[128 * 36];
    const int bm = blockIdx.y * 128, bn = blockIdx.x * 128;
    const int tid = threadIdx.x;
    const int wid = tid >> 5, lane = tid & 31;
    const int wm = (wid >> 1) * 32, wn = (wid & 1) * 64;
    const int lq = lane >> 2, lr = lane & 3;

    float acc[2][8][4];
#pragma unroll
    for (int mf = 0; mf < 2; mf++)
#pragma unroll
        for (int nf = 0; nf < 8; nf++)
#pragma unroll
            for (int j = 0; j < 4; j++) acc[mf][nf][j] = 0.f;

    const int row = tid >> 3;            // 0..31
    const int kc = (tid & 7) * 4;        // 0,4,..28
    const int icb = (kc & 24) | ((kc & 4) >> 2);

    float4 pa[4], pb[4];
#pragma unroll
    for (int p = 0; p < 4; p++) {
        pa[p] = *(const float4*)(A + (size_t)(bm + row + 32 * p) * K + kc);
        pb[p] = *(const float4*)(B + (size_t)(bn + row + 32 * p) * K + kc);
    }

    for (int k0 = 0; k0 < K; k0 += 32) {
        __syncthreads();
#pragma unroll
        for (int p = 0; p < 4; p++) {
            unsigned* as = &As[(row + 32 * p) * 36 + icb];
            as[0] = f2tf(pa[p].x); as[2] = f2tf(pa[p].y);
            as[4] = f2tf(pa[p].z); as[6] = f2tf(pa[p].w);
            unsigned* bs = &Bs[(row + 32 * p) * 36 + icb];
            bs[0] = f2tf(pb[p].x); bs[2] = f2tf(pb[p].y);
            bs[4] = f2tf(pb[p].z); bs[6] = f2tf(pb[p].w);
        }
        __syncthreads();
        if (k0 + 32 < K) {
#pragma unroll
            for (int p = 0; p < 4; p++) {
                pa[p] = *(const float4*)(A + (size_t)(bm + row + 32 * p) * K + k0 + 32 + kc);
                pb[p] = *(const float4*)(B + (size_t)(bn + row + 32 * p) * K + k0 + 32 + kc);
            }
        }
#pragma unroll
        for (int ks = 0; ks < 4; ks++) {
            unsigned a[2][4];
#pragma unroll
            for (int mf = 0; mf < 2; mf++) {
                uint2 a02 = *(const uint2*)&As[(wm + mf * 16 + lq) * 36 + ks * 8 + lr * 2];
                uint2 a13 = *(const uint2*)&As[(wm + mf * 16 + 8 + lq) * 36 + ks * 8 + lr * 2];
                a[mf][0] = a02.x; a[mf][1] = a13.x; a[mf][2] = a02.y; a[mf][3] = a13.y;
            }
#pragma unroll
            for (int nf = 0; nf < 8; nf++) {
                uint2 b = *(const uint2*)&Bs[(wn + nf * 8 + lq) * 36 + ks * 8 + lr * 2];
                mma_tf32(acc[0][nf], a[0][0], a[0][1], a[0][2], a[0][3], b.x, b.y);
                mma_tf32(acc[1][nf], a[1][0], a[1][1], a[1][2], a[1][3], b.x, b.y);
            }
        }
    }
#pragma unroll
    for (int mf = 0; mf < 2; mf++)
#pragma unroll
        for (int nf = 0; nf < 8; nf++) {
            float* c0 = C + (size_t)(bm + wm + mf * 16 + lq) * N + bn + wn + nf * 8 + lr * 2;
            c0[0] = acc[mf][nf][0]; c0[1] = acc[mf][nf][1];
            float* c1 = c0 + 8 * (size_t)N;
            c1[0] = acc[mf][nf][2]; c1[1] = acc[mf][nf][3];
        }
}

// ---------------- RMSNorm + rotary + V blend, tf32 + interleave output -------
__global__ __launch_bounds__(128) void qkv_post(const float* __restrict__ qkv,
                                                const float* __restrict__ ve,
                                                const float* __restrict__ lambdas,
                                                float* __restrict__ Q,
                                                float* __restrict__ K,
                                                float* __restrict__ V) {
    const int t = blockIdx.x, h = blockIdx.y, d = threadIdx.x;
    const int lane = d & 31, wid = d >> 5;
    const float* base = qkv + (size_t)t * (3 * D_MODEL) + h * HDIM;

    float qv = base[d];
    float kv = base[D_MODEL + d];
    float vv = base[2 * D_MODEL + d];

    float s1 = qv * qv, s2 = kv * kv;
#pragma unroll
    for (int o = 16; o; o >>= 1) {
        s1 += __shfl_xor_sync(0xffffffffu, s1, o);
        s2 += __shfl_xor_sync(0xffffffffu, s2, o);
    }
    __shared__ float w1[4], w2[4];
    if (lane == 0) { w1[wid] = s1; w2[wid] = s2; }
    __syncthreads();
    float sq = w1[0] + w1[1] + w1[2] + w1[3];
    float sk = w2[0] + w2[1] + w2[2] + w2[3];
    const float eps = 1.1920929e-7f;
    float rq = rsqrtf(sq * (1.0f / 128.0f) + eps);
    float rk = rsqrtf(sk * (1.0f / 128.0f) + eps);

    __shared__ float qs[128], ks[128];
    qs[d] = qv * rq; ks[d] = kv * rk;
    __syncthreads();

    int j = d & 63;
    float ang = (j < 32) ? powf(1.0f / 1024.0f, (float)j / 31.0f) : 0.0f;
    float theta = (float)t * ang;
    float c, s;
    sincosf(theta, &s, &c);

    float qo, ko;
    if (d < 64) {
        qo =  qs[d] * c + qs[d + 64] * s;
        ko =  ks[d] * c + ks[d + 64] * s;
    } else {
        qo = -qs[d - 64] * s + qs[d] * c;
        ko = -ks[d - 64] * s + ks[d] * c;
    }

    float l0 = lambdas[0], l1 = lambdas[1];
    float vo = l0 * vv + l1 * ve[(size_t)t * D_MODEL + h * HDIM + d];

    size_t rb = ((size_t)h * T_LEN + t) * HDIM;
    int di = icol8(d);
    Q[rb + di] = __uint_as_float(f2tf(qo * ATTN_SCALE));
    K[rb + di] = __uint_as_float(f2tf(ko));
    V[rb + d]  = __uint_as_float(f2tf(vo));
}

// ---------------- tf32 mma causal flash attention ----------------------------
// grid (32, 8) reversed, 256 thr (8 warps). CTA = 128 queries, key tiles of 64.
// Warp w: softmax rows [w*16, w*16+16); PV computes O^T rows d in [w*16, w*16+16).
#define QS  132
#define PSS 72
__global__ __launch_bounds__(256) void attn_tf32(const float* __restrict__ Q,
                                                 const float* __restrict__ K,
                                                 const float* __restrict__ V,
                                                 float* __restrict__ Y) {
    extern __shared__ unsigned sm[];
    unsigned* Qs = sm;                     // 128 x QS
    unsigned* Ks = Qs + 128 * QS;          // 64 x QS
    unsigned* Vs = Ks + 64 * QS;           // 64 x QS
    unsigned* Ps = Vs + 64 * QS;           // 128 x PSS
    float* Rs = (float*)(Ps + 128 * PSS);  // 128 rescale
    float* Li = Rs + 128;                  // 128 1/l

    const int h  = blockIdx.y;
    const int qb = ((int)gridDim.x - 1 - (int)blockIdx.x) * 128;
    const int tid = threadIdx.x, wid = tid >> 5, lane = tid & 31;
    const int lq = lane >> 2, lr = lane & 3;
    const int qw = wid * 16;               // this warp's q-row band (softmax)
    const int dw = wid * 16;               // this warp's d band (PV / epilogue)

    const uint4* Qg = (const uint4*)(Q + (size_t)h * T_LEN * HDIM);
    const uint4* Kg = (const uint4*)(K + (size_t)h * T_LEN * HDIM);
    const uint4* Vg = (const uint4*)(V + (size_t)h * T_LEN * HDIM);

    // load Q tile 128x128 (already tf32+interleaved)
#pragma unroll
    for (int p = 0; p < 16; p++) {
        int e = tid + 256 * p;
        int r = e >> 5, c = (e & 31) * 4;
        *(uint4*)&Qs[r * QS + c] = Qg[((size_t)(qb + r) * HDIM + c) >> 2];
    }

    const int ic0 = icol8(2 * lr);
    const int ic1 = icol8(2 * lr + 1);

    float ofr[16][4];
#pragma unroll
    for (int nf = 0; nf < 16; nf++)
#pragma unroll
        for (int j = 0; j < 4; j++) ofr[nf][j] = 0.f;
    float m0 = -1e30f, m1 = -1e30f, l0 = 0.f, l1 = 0.f;

    const int ntiles = qb / 64 + 2;
    for (int it = 0; it < ntiles; it++) {
        const int s0 = it * 64;
        __syncthreads();
#pragma unroll
        for (int p = 0; p < 8; p++) {
            int e = tid + 256 * p;
            int r = e >> 5, c = (e & 31) * 4;
            *(uint4*)&Ks[r * QS + c] = Kg[((size_t)(s0 + r) * HDIM + c) >> 2];
            *(uint4*)&Vs[r * QS + c] = Vg[((size_t)(s0 + r) * HDIM + c) >> 2];
        }
        __syncthreads();

        // ---- S = Q K^T for this warp's 16 rows ----
        float sfr[8][4];
#pragma unroll
        for (int nf = 0; nf < 8; nf++)
#pragma unroll
            for (int j = 0; j < 4; j++) sfr[nf][j] = 0.f;
#pragma unroll
        for (int ks = 0; ks < 16; ks++) {
            uint2 a02 = *(const uint2*)&Qs[(qw + lq) * QS + ks * 8 + lr * 2];
            uint2 a13 = *(const uint2*)&Qs[(qw + 8 + lq) * QS + ks * 8 + lr * 2];
#pragma unroll
            for (int nf = 0; nf < 8; nf++) {
                uint2 b = *(const uint2*)&Ks[(nf * 8 + lq) * QS + ks * 8 + lr * 2];
                mma_tf32(sfr[nf], a02.x, a13.x, a02.y, a13.y, b.x, b.y);
            }
        }

        // ---- masked online softmax (scores already *ATTN_SCALE via Q) ----
        const int q0 = qb + qw + lq, q1 = q0 + 8;
        const bool needmask = (s0 + 63) > (qb + qw);
        float r0 = -1e30f, r1 = -1e30f;
        if (needmask) {
#pragma unroll
            for (int nf = 0; nf < 8; nf++) {
                int sA = s0 + nf * 8 + 2 * lr, sB = sA + 1;
                if (sA > q0) sfr[nf][0] = -1e30f;
                if (sB > q0) sfr[nf][1] = -1e30f;
                if (sA > q1) sfr[nf][2] = -1e30f;
                if (sB > q1) sfr[nf][3] = -1e30f;
            }
        }
#pragma unroll
        for (int nf = 0; nf < 8; nf++) {
            r0 = fmaxf(r0, fmaxf(sfr[nf][0], sfr[nf][1]));
            r1 = fmaxf(r1, fmaxf(sfr[nf][2], sfr[nf][3]));
        }
        r0 = fmaxf(r0, __shfl_xor_sync(0xffffffffu, r0, 1));
        r0 = fmaxf(r0, __shfl_xor_sync(0xffffffffu, r0, 2));
        r1 = fmaxf(r1, __shfl_xor_sync(0xffffffffu, r1, 1));
        r1 = fmaxf(r1, __shfl_xor_sync(0xffffffffu, r1, 2));
        float mn0 = fmaxf(m0, r0), mn1 = fmaxf(m1, r1);
        float rs0 = fexp(m0 - mn0), rs1 = fexp(m1 - mn1);
        float sum0 = 0.f, sum1 = 0.f;
#pragma unroll
        for (int nf = 0; nf < 8; nf++) {
            float p00 = fexp(sfr[nf][0] - mn0);
            float p01 = fexp(sfr[nf][1] - mn0);
            float p10 = fexp(sfr[nf][2] - mn1);
            float p11 = fexp(sfr[nf][3] - mn1);
            sum0 += p00 + p01; sum1 += p10 + p11;
            Ps[(qw + lq) * PSS + nf * 8 + ic0]     = f2tf(p00);
            Ps[(qw + lq) * PSS + nf * 8 + ic1]     = f2tf(p01);
            Ps[(qw + 8 + lq) * PSS + nf * 8 + ic0] = f2tf(p10);
            Ps[(qw + 8 + lq) * PSS + nf * 8 + ic1] = f2tf(p11);
        }
        sum0 += __shfl_xor_sync(0xffffffffu, sum0, 1);
        sum0 += __shfl_xor_sync(0xffffffffu, sum0, 2);
        sum1 += __shfl_xor_sync(0xffffffffu, sum1, 1);
        sum1 += __shfl_xor_sync(0xffffffffu, sum1, 2);
        l0 = l0 * rs0 + sum0; m0 = mn0;
        l1 = l1 * rs1 + sum1; m1 = mn1;
        if (lr == 0) { Rs[qw + lq] = rs0; Rs[qw + 8 + lq] = rs1; }
        __syncthreads();

        // ---- rescale O^T (cols = q) ----
#pragma unroll
        for (int nf = 0; nf < 16; nf++) {
            float2 rr = *(const float2*)&Rs[nf * 8 + lr * 2];
            ofr[nf][0] *= rr.x; ofr[nf][1] *= rr.y;
            ofr[nf][2] *= rr.x; ofr[nf][3] *= rr.y;
        }

        // ---- O^T += V^T P^T ----
#pragma unroll
        for (int ks = 0; ks < 8; ks++) {
            unsigned a0 = Vs[(ks * 8 + lr) * QS + dw + lq];
            unsigned a1 = Vs[(ks * 8 + lr) * QS + dw + lq + 8];
            unsigned a2 = Vs[(ks * 8 + lr + 4) * QS + dw + lq];
            unsigned a3 = Vs[(ks * 8 + lr + 4) * QS + dw + lq + 8];
#pragma unroll
            for (int nf = 0; nf < 16; nf++) {
                uint2 b = *(const uint2*)&Ps[(nf * 8 + lq) * PSS + ks * 8 + lr * 2];
                mma_tf32(ofr[nf], a0, a1, a2, a3, b.x, b.y);
            }
        }
    }

    // ---- epilogue ----
    if (lr == 0) { Li[qw + lq] = 1.f / l0; Li[qw + 8 + lq] = 1.f / l1; }
    __syncthreads();
#pragma unroll
    for (int nf = 0; nf < 16; nf++) {
        float2 li = *(const float2*)&Li[nf * 8 + lr * 2];
        int q = qb + nf * 8 + lr * 2;
        float* ya = Y + (size_t)q * D_MODEL + h * HDIM + dw + lq;
        float* yb = ya + D_MODEL;
        ya[0] = ofr[nf][0] * li.x;
        yb[0] = ofr[nf][1] * li.y;
        ya[8] = ofr[nf][2] * li.x;
        yb[8] = ofr[nf][3] * li.y;
    }
}

// ---------------- launch ------------------------------------------------------
extern "C" void kernel_launch(void* const* d_in, const int* in_sizes, int n_in,
                              void* d_out, int out_size) {
    const float* x        = (const float*)d_in[0];
    const float* ve       = (const float*)d_in[1];
    const float* qkv_w    = (const float*)d_in[2];
    const float* lambdas  = (const float*)d_in[3];
    const float* c_proj_w = (const float*)d_in[4];
    float* out = (float*)d_out;

    float *p_qkv, *p_q, *p_k, *p_v, *p_y;
    cudaGetSymbolAddress((void**)&p_qkv, g_qkv);
    cudaGetSymbolAddress((void**)&p_q, g_q);
    cudaGetSymbolAddress((void**)&p_k, g_k);
    cudaGetSymbolAddress((void**)&p_v, g_v);
    cudaGetSymbolAddress((void**)&p_y, g_y);

    const int attn_smem = (128 * QS + 64 * QS + 64 * QS + 128 * PSS + 256) * 4;
    static bool attr_set = false;
    if (!attr_set) {
        cudaFuncSetAttribute(attn_tf32, cudaFuncAttributeMaxDynamicSharedMemorySize,
                             attn_smem);
        attr_set = true;
    }

    gemm_nt_tf32<<<dim3(3 * D_MODEL / 128, T_LEN / 128), 256>>>(
        x, qkv_w, p_qkv, T_LEN, 3 * D_MODEL, D_MODEL);

    qkv_post<<<dim3(T_LEN, NHEAD), 128>>>(p_qkv, ve, lambdas, p_q, p_k, p_v);

    attn_tf32<<<dim3(T_LEN / 128, NHEAD), 256, attn_smem>>>(p_q, p_k, p_v, p_y);

    gemm_nt_tf32<<<dim3(D_MODEL / 128, T_LEN / 128), 256>>>(
        p_y, c_proj_w, out, T_LEN, D_MODEL, D_MODEL);
}

// round 4
// speedup vs baseline: 4.4998x; 1.0989x over previous
#include <cuda_runtime.h>
#include <cstdint>

#define T_LEN   4096
#define D_MODEL 1024
#define NHEAD   8
#define HDIM    128
#define ATTN_SCALE 0.12f

// ---------------- tf32 mma helpers ------------------------------------------
__device__ __forceinline__ unsigned f2tf(float f) {
    unsigned u; asm("cvt.rna.tf32.f32 %0, %1;" : "=r"(u) : "f"(f)); return u;
}
__device__ __forceinline__ void mma_tf32(float* d,
    unsigned a0, unsigned a1, unsigned a2, unsigned a3,
    unsigned b0, unsigned b1) {
    asm volatile("mma.sync.aligned.m16n8k8.row.col.f32.tf32.tf32.f32 "
        "{%0,%1,%2,%3},{%4,%5,%6,%7},{%8,%9},{%0,%1,%2,%3};"
        : "+f"(d[0]), "+f"(d[1]), "+f"(d[2]), "+f"(d[3])
        : "r"(a0), "r"(a1), "r"(a2), "r"(a3), "r"(b0), "r"(b1));
}
__device__ __forceinline__ int icol8(int k) {
    return (k & ~7) | ((k & 3) << 1) | ((k >> 2) & 1);
}
__device__ __forceinline__ float fexp(float x) {
    float t = x * 1.4426950408889634f;
    float f = floorf(t);
    float r = t - f;
    float p = 1.3400000e-3f;
    p = fmaf(p, r, 9.6770508e-3f);
    p = fmaf(p, r, 5.5503310e-2f);
    p = fmaf(p, r, 2.4022652e-1f);
    p = fmaf(p, r, 6.9314718e-1f);
    p = fmaf(p, r, 1.0f);
    int e = (int)f;
    e = max(e, -127);
    float s = __int_as_float((unsigned)(e + 127) << 23);
    return p * s;
}
// ---------------- cp.async helpers -------------------------------------------
__device__ __forceinline__ void cp16(void* smem_ptr, const void* gptr) {
    unsigned sa = (unsigned)__cvta_generic_to_shared(smem_ptr);
    asm volatile("cp.async.cg.shared.global [%0], [%1], 16;" :: "r"(sa), "l"(gptr));
}
#define CP_COMMIT() asm volatile("cp.async.commit_group;")
#define CP_WAIT(N)  asm volatile("cp.async.wait_group %0;" :: "n"(N))

// ---------------- scratch ----------------------------------------------------
__device__ float g_qkv[(size_t)T_LEN * 3 * D_MODEL];
__device__ float g_q[(size_t)NHEAD * T_LEN * HDIM];   // tf32, interleaved, *scale
__device__ float g_k[(size_t)NHEAD * T_LEN * HDIM];   // tf32, interleaved
__device__ float g_v[(size_t)NHEAD * T_LEN * HDIM];   // tf32, natural
__device__ float g_y[(size_t)T_LEN * D_MODEL];        // tf32, interleaved
__device__ float g_xi[(size_t)T_LEN * D_MODEL];       // preconv x
__device__ float g_wi[(size_t)3 * D_MODEL * D_MODEL]; // preconv qkv_w
__device__ float g_cpi[(size_t)D_MODEL * D_MODEL];    // preconv c_proj_w

// ---------------- pre-pass: tf32 round + icol8 interleave (K=1024) -----------
__global__ __launch_bounds__(256) void conv_ilv(const float* __restrict__ in,
                                                float* __restrict__ out, int n4) {
    int i = blockIdx.x * 256 + threadIdx.x;
    if (i >= n4) return;
    float4 v = ((const float4*)in)[i];
    int idx = i * 4;
    int row = idx >> 10;
    int c = idx & 1023;
    int base = row * 1024 + (c & ~7);
    int h = (c >> 2) & 1;
    out[base + h + 0] = __uint_as_float(f2tf(v.x));
    out[base + h + 2] = __uint_as_float(f2tf(v.y));
    out[base + h + 4] = __uint_as_float(f2tf(v.z));
    out[base + h + 6] = __uint_as_float(f2tf(v.w));
}

// ---------------- tf32 NT GEMM v3: preconverted inputs, cp.async 3-stage -----
// C[M,N] = A[M,K] B[N,K]^T. 256 thr, 8 warps (4Mx2N), warp 32x64, BK=16.
#define GST 20            // smem row stride (16 + 4 pad)
#define GSTAGE (128 * GST) // words per matrix per stage (2560)
__global__ __launch_bounds__(256, 2) void gemm3(const float* __restrict__ A,
                                                const float* __restrict__ B,
                                                float* __restrict__ C,
                                                int M, int N, int K) {
    extern __shared__ unsigned smu[];
    const int bm = blockIdx.y * 128, bn = blockIdx.x * 128;
    const int tid = threadIdx.x;
    const int wid = tid >> 5, lane = tid & 31;
    const int wm = (wid >> 1) * 32, wn = (wid & 1) * 64;
    const int lq = lane >> 2, lr = lane & 3;

    const int row0 = tid >> 2;            // slot rows
    const int ch0  = (tid & 3) * 4;       // col chunk (floats)

    float acc[2][8][4];
#pragma unroll
    for (int mf = 0; mf < 2; mf++)
#pragma unroll
        for (int nf = 0; nf < 8; nf++)
#pragma unroll
            for (int j = 0; j < 4; j++) acc[mf][nf][j] = 0.f;

    const int nk = K >> 4;   // 16-wide k steps

    auto issue = [&](int it, int buf) {
        unsigned* sA = smu + buf * (2 * GSTAGE);
        unsigned* sB = sA + GSTAGE;
        int k0 = it << 4;
#pragma unroll
        for (int p = 0; p < 2; p++) {
            int r = row0 + p * 64;
            cp16(&sA[r * GST + ch0], A + (size_t)(bm + r) * K + k0 + ch0);
            cp16(&sB[r * GST + ch0], B + (size_t)(bn + r) * K + k0 + ch0);
        }
    };

    issue(0, 0); CP_COMMIT();
    issue(1, 1); CP_COMMIT();

    for (int it = 0; it < nk; it++) {
        CP_WAIT(1);
        __syncthreads();
        if (it + 2 < nk) issue(it + 2, (it + 2) % 3);
        CP_COMMIT();

        const unsigned* sA = smu + (it % 3) * (2 * GSTAGE);
        const unsigned* sB = sA + GSTAGE;
#pragma unroll
        for (int ks = 0; ks < 2; ks++) {
            unsigned a[2][4];
#pragma unroll
            for (int mf = 0; mf < 2; mf++) {
                uint2 a02 = *(const uint2*)&sA[(wm + mf * 16 + lq) * GST + ks * 8 + lr * 2];
                uint2 a13 = *(const uint2*)&sA[(wm + mf * 16 + 8 + lq) * GST + ks * 8 + lr * 2];
                a[mf][0] = a02.x; a[mf][1] = a13.x; a[mf][2] = a02.y; a[mf][3] = a13.y;
            }
#pragma unroll
            for (int nf = 0; nf < 8; nf++) {
                uint2 b = *(const uint2*)&sB[(wn + nf * 8 + lq) * GST + ks * 8 + lr * 2];
                mma_tf32(acc[0][nf], a[0][0], a[0][1], a[0][2], a[0][3], b.x, b.y);
                mma_tf32(acc[1][nf], a[1][0], a[1][1], a[1][2], a[1][3], b.x, b.y);
            }
        }
    }
#pragma unroll
    for (int mf = 0; mf < 2; mf++)
#pragma unroll
        for (int nf = 0; nf < 8; nf++) {
            float* c0 = C + (size_t)(bm + wm + mf * 16 + lq) * N + bn + wn + nf * 8 + lr * 2;
            c0[0] = acc[mf][nf][0]; c0[1] = acc[mf][nf][1];
            float* c1 = c0 + 8 * (size_t)N;
            c1[0] = acc[mf][nf][2]; c1[1] = acc[mf][nf][3];
        }
}

// ---------------- RMSNorm + rotary + V blend ---------------------------------
__global__ __launch_bounds__(128) void qkv_post(const float* __restrict__ qkv,
                                                const float* __restrict__ ve,
                                                const float* __restrict__ lambdas,
                                                float* __restrict__ Q,
                                                float* __restrict__ K,
                                                float* __restrict__ V) {
    const int t = blockIdx.x, h = blockIdx.y, d = threadIdx.x;
    const int lane = d & 31, wid = d >> 5;
    const float* base = qkv + (size_t)t * (3 * D_MODEL) + h * HDIM;

    float qv = base[d];
    float kv = base[D_MODEL + d];
    float vv = base[2 * D_MODEL + d];

    float s1 = qv * qv, s2 = kv * kv;
#pragma unroll
    for (int o = 16; o; o >>= 1) {
        s1 += __shfl_xor_sync(0xffffffffu, s1, o);
        s2 += __shfl_xor_sync(0xffffffffu, s2, o);
    }
    __shared__ float w1[4], w2[4];
    if (lane == 0) { w1[wid] = s1; w2[wid] = s2; }
    __syncthreads();
    float sq = w1[0] + w1[1] + w1[2] + w1[3];
    float sk = w2[0] + w2[1] + w2[2] + w2[3];
    const float eps = 1.1920929e-7f;
    float rq = rsqrtf(sq * (1.0f / 128.0f) + eps);
    float rk = rsqrtf(sk * (1.0f / 128.0f) + eps);

    __shared__ float qs[128], ks[128];
    qs[d] = qv * rq; ks[d] = kv * rk;
    __syncthreads();

    int j = d & 63;
    float ang = (j < 32) ? exp2f((float)j * (-10.0f / 31.0f)) : 0.0f;
    float theta = (float)t * ang;
    float c, s;
    sincosf(theta, &s, &c);

    float qo, ko;
    if (d < 64) {
        qo =  qs[d] * c + qs[d + 64] * s;
        ko =  ks[d] * c + ks[d + 64] * s;
    } else {
        qo = -qs[d - 64] * s + qs[d] * c;
        ko = -ks[d - 64] * s + ks[d] * c;
    }

    float l0 = lambdas[0], l1 = lambdas[1];
    float vo = l0 * vv + l1 * ve[(size_t)t * D_MODEL + h * HDIM + d];

    size_t rb = ((size_t)h * T_LEN + t) * HDIM;
    int di = icol8(d);
    Q[rb + di] = __uint_as_float(f2tf(qo * ATTN_SCALE));
    K[rb + di] = __uint_as_float(f2tf(ko));
    V[rb + d]  = __uint_as_float(f2tf(vo));
}

// ---------------- tf32 mma causal flash attention, pipelined -----------------
// 256 thr, 8 warps. CTA = 128 q rows; key tiles of 64, 2-stage cp.async.
#define KVS 132
#define KVW (64 * KVS)
#define PSS 72
// smem words: Kb[2*KVW] @0, Vb[2*KVW] @2*KVW, Ps[128*PSS] @4*KVW, RsLi @+9216
#define SM_PS   (4 * KVW)
#define SM_RS   (SM_PS + 128 * PSS)
#define SM_TOT  (SM_RS + 256)
__global__ __launch_bounds__(256) void attn_tf32(const float* __restrict__ Q,
                                                 const float* __restrict__ K,
                                                 const float* __restrict__ V,
                                                 float* __restrict__ Y) {
    extern __shared__ unsigned sm[];
    unsigned* Ps = sm + SM_PS;
    float* Rs = (float*)(sm + SM_RS);
    float* Li = Rs + 128;

    const int h  = blockIdx.y;
    const int qb = ((int)gridDim.x - 1 - (int)blockIdx.x) * 128;
    const int tid = threadIdx.x, wid = tid >> 5, lane = tid & 31;
    const int lq = lane >> 2, lr = lane & 3;
    const int qw = wid * 16;
    const int dw = wid * 16;

    const uint4* Qg = (const uint4*)(Q + (size_t)h * T_LEN * HDIM);
    const float* Kh = K + (size_t)h * T_LEN * HDIM;
    const float* Vh = V + (size_t)h * T_LEN * HDIM;

    // ---- stage Q tile into smem (reuse K/V area), extract per-warp frags ----
#pragma unroll
    for (int p = 0; p < 16; p++) {
        int e = tid + 256 * p;
        int r = e >> 5, c = (e & 31) * 4;
        *(uint4*)&sm[r * KVS + c] = Qg[((size_t)(qb + r) * HDIM + c) >> 2];
    }
    __syncthreads();
    unsigned qa[16][4];
#pragma unroll
    for (int ks = 0; ks < 16; ks++) {
        uint2 a02 = *(const uint2*)&sm[(qw + lq) * KVS + ks * 8 + lr * 2];
        uint2 a13 = *(const uint2*)&sm[(qw + 8 + lq) * KVS + ks * 8 + lr * 2];
        qa[ks][0] = a02.x; qa[ks][1] = a13.x; qa[ks][2] = a02.y; qa[ks][3] = a13.y;
    }
    __syncthreads();

    const int ic0 = icol8(2 * lr);
    const int ic1 = icol8(2 * lr + 1);

    float ofr[16][4];
#pragma unroll
    for (int nf = 0; nf < 16; nf++)
#pragma unroll
        for (int j = 0; j < 4; j++) ofr[nf][j] = 0.f;
    float m0 = -1e30f, m1 = -1e30f, l0 = 0.f, l1 = 0.f;

    const int ntiles = qb / 64 + 2;

    auto issue_kv = [&](int s0, int buf) {
        unsigned* Kb = sm + buf * KVW;
        unsigned* Vb = sm + 2 * KVW + buf * KVW;
#pragma unroll
        for (int p = 0; p < 8; p++) {
            int e = tid + 256 * p;
            int r = e >> 5, c = (e & 31) * 4;
            cp16(&Kb[r * KVS + c], Kh + (size_t)(s0 + r) * HDIM + c);
            cp16(&Vb[r * KVS + c], Vh + (size_t)(s0 + r) * HDIM + c);
        }
    };

    issue_kv(0, 0); CP_COMMIT();

    for (int it = 0; it < ntiles; it++) {
        const int s0 = it * 64;
        const int buf = it & 1;
        CP_WAIT(0);
        __syncthreads();                       // sync#1
        if (it + 1 < ntiles) issue_kv(s0 + 64, buf ^ 1);
        CP_COMMIT();

        const unsigned* Kb = sm + buf * KVW;
        const unsigned* Vb = sm + 2 * KVW + buf * KVW;

        // ---- S = Q K^T ----
        float sfr[8][4];
#pragma unroll
        for (int nf = 0; nf < 8; nf++)
#pragma unroll
            for (int j = 0; j < 4; j++) sfr[nf][j] = 0.f;
#pragma unroll
        for (int ks = 0; ks < 16; ks++) {
#pragma unroll
            for (int nf = 0; nf < 8; nf++) {
                uint2 b = *(const uint2*)&Kb[(nf * 8 + lq) * KVS + ks * 8 + lr * 2];
                mma_tf32(sfr[nf], qa[ks][0], qa[ks][1], qa[ks][2], qa[ks][3], b.x, b.y);
            }
        }

        // ---- masked online softmax ----
        const int q0 = qb + qw + lq, q1 = q0 + 8;
        const bool needmask = (s0 + 63) > (qb + qw);
        float r0 = -1e30f, r1 = -1e30f;
        if (needmask) {
#pragma unroll
            for (int nf = 0; nf < 8; nf++) {
                int sA = s0 + nf * 8 + 2 * lr, sB = sA + 1;
                if (sA > q0) sfr[nf][0] = -1e30f;
                if (sB > q0) sfr[nf][1] = -1e30f;
                if (sA > q1) sfr[nf][2] = -1e30f;
                if (sB > q1) sfr[nf][3] = -1e30f;
            }
        }
#pragma unroll
        for (int nf = 0; nf < 8; nf++) {
            r0 = fmaxf(r0, fmaxf(sfr[nf][0], sfr[nf][1]));
            r1 = fmaxf(r1, fmaxf(sfr[nf][2], sfr[nf][3]));
        }
        r0 = fmaxf(r0, __shfl_xor_sync(0xffffffffu, r0, 1));
        r0 = fmaxf(r0, __shfl_xor_sync(0xffffffffu, r0, 2));
        r1 = fmaxf(r1, __shfl_xor_sync(0xffffffffu, r1, 1));
        r1 = fmaxf(r1, __shfl_xor_sync(0xffffffffu, r1, 2));
        float mn0 = fmaxf(m0, r0), mn1 = fmaxf(m1, r1);
        float rs0 = fexp(m0 - mn0), rs1 = fexp(m1 - mn1);
        float sum0 = 0.f, sum1 = 0.f;
#pragma unroll
        for (int nf = 0; nf < 8; nf++) {
            float p00 = fexp(sfr[nf][0] - mn0);
            float p01 = fexp(sfr[nf][1] - mn0);
            float p10 = fexp(sfr[nf][2] - mn1);
            float p11 = fexp(sfr[nf][3] - mn1);
            sum0 += p00 + p01; sum1 += p10 + p11;
            Ps[(qw + lq) * PSS + nf * 8 + ic0]     = f2tf(p00);
            Ps[(qw + lq) * PSS + nf * 8 + ic1]     = f2tf(p01);
            Ps[(qw + 8 + lq) * PSS + nf * 8 + ic0] = f2tf(p10);
            Ps[(qw + 8 + lq) * PSS + nf * 8 + ic1] = f2tf(p11);
        }
        sum0 += __shfl_xor_sync(0xffffffffu, sum0, 1);
        sum0 += __shfl_xor_sync(0xffffffffu, sum0, 2);
        sum1 += __shfl_xor_sync(0xffffffffu, sum1, 1);
        sum1 += __shfl_xor_sync(0xffffffffu, sum1, 2);
        l0 = l0 * rs0 + sum0; m0 = mn0;
        l1 = l1 * rs1 + sum1; m1 = mn1;
        if (lr == 0) { Rs[qw + lq] = rs0; Rs[qw + 8 + lq] = rs1; }
        __syncthreads();                       // sync#2: Ps/Rs ready

        // ---- rescale O^T ----
#pragma unroll
        for (int nf = 0; nf < 16; nf++) {
            float2 rr = *(const float2*)&Rs[nf * 8 + lr * 2];
            ofr[nf][0] *= rr.x; ofr[nf][1] *= rr.y;
            ofr[nf][2] *= rr.x; ofr[nf][3] *= rr.y;
        }

        // ---- O^T += V^T P^T ----
#pragma unroll
        for (int ks = 0; ks < 8; ks++) {
            unsigned a0 = Vb[(ks * 8 + lr) * KVS + dw + lq];
            unsigned a1 = Vb[(ks * 8 + lr) * KVS + dw + lq + 8];
            unsigned a2 = Vb[(ks * 8 + lr + 4) * KVS + dw + lq];
            unsigned a3 = Vb[(ks * 8 + lr + 4) * KVS + dw + lq + 8];
#pragma unroll
            for (int nf = 0; nf < 16; nf++) {
                uint2 b = *(const uint2*)&Ps[(nf * 8 + lq) * PSS + ks * 8 + lr * 2];
                mma_tf32(ofr[nf], a0, a1, a2, a3, b.x, b.y);
            }
        }
    }

    // ---- epilogue: normalize, tf32-round, icol8-interleave into Y -----------
    if (lr == 0) { Li[qw + lq] = 1.f / l0; Li[qw + 8 + lq] = 1.f / l1; }
    __syncthreads();
    const int lqp = ((lq & 3) << 1) | (lq >> 2);   // icol8 within 8-group
    const int colbase = h * HDIM + dw;
#pragma unroll
    for (int nf = 0; nf < 16; nf++) {
        float2 li = *(const float2*)&Li[nf * 8 + lr * 2];
        int q = qb + nf * 8 + lr * 2;
        float* ya = Y + (size_t)q * D_MODEL;
        float* yb = ya + D_MODEL;
        ya[colbase + lqp]     = __uint_as_float(f2tf(ofr[nf][0] * li.x));
        yb[colbase + lqp]     = __uint_as_float(f2tf(ofr[nf][1] * li.y));
        ya[colbase + 8 + lqp] = __uint_as_float(f2tf(ofr[nf][2] * li.x));
        yb[colbase + 8 + lqp] = __uint_as_float(f2tf(ofr[nf][3] * li.y));
    }
}

// ---------------- launch ------------------------------------------------------
extern "C" void kernel_launch(void* const* d_in, const int* in_sizes, int n_in,
                              void* d_out, int out_size) {
    const float* x        = (const float*)d_in[0];
    const float* ve       = (const float*)d_in[1];
    const float* qkv_w    = (const float*)d_in[2];
    const float* lambdas  = (const float*)d_in[3];
    const float* c_proj_w = (const float*)d_in[4];
    float* out = (float*)d_out;

    float *p_qkv, *p_q, *p_k, *p_v, *p_y, *p_xi, *p_wi, *p_cpi;
    cudaGetSymbolAddress((void**)&p_qkv, g_qkv);
    cudaGetSymbolAddress((void**)&p_q, g_q);
    cudaGetSymbolAddress((void**)&p_k, g_k);
    cudaGetSymbolAddress((void**)&p_v, g_v);
    cudaGetSymbolAddress((void**)&p_y, g_y);
    cudaGetSymbolAddress((void**)&p_xi, g_xi);
    cudaGetSymbolAddress((void**)&p_wi, g_wi);
    cudaGetSymbolAddress((void**)&p_cpi, g_cpi);

    const int gemm_smem = 3 * 2 * GSTAGE * 4;       // 61440 B
    const int attn_smem = SM_TOT * 4;               // ~173 KB
    static bool attr_set = false;
    if (!attr_set) {
        cudaFuncSetAttribute(gemm3, cudaFuncAttributeMaxDynamicSharedMemorySize,
                             gemm_smem);
        cudaFuncSetAttribute(attn_tf32, cudaFuncAttributeMaxDynamicSharedMemorySize,
                             attn_smem);
        attr_set = true;
    }

    // pre-pass conversions (K = 1024 for all)
    conv_ilv<<<4096, 256>>>(x, p_xi, T_LEN * D_MODEL / 4);
    conv_ilv<<<3072, 256>>>(qkv_w, p_wi, 3 * D_MODEL * D_MODEL / 4);
    conv_ilv<<<1024, 256>>>(c_proj_w, p_cpi, D_MODEL * D_MODEL / 4);

    gemm3<<<dim3(3 * D_MODEL / 128, T_LEN / 128), 256, gemm_smem>>>(
        p_xi, p_wi, p_qkv, T_LEN, 3 * D_MODEL, D_MODEL);

    qkv_post<<<dim3(T_LEN, NHEAD), 128>>>(p_qkv, ve, lambdas, p_q, p_k, p_v);

    attn_tf32<<<dim3(T_LEN / 128, NHEAD), 256, attn_smem>>>(p_q, p_k, p_v, p_y);

    gemm3<<<dim3(D_MODEL / 128, T_LEN / 128), 256, gemm_smem>>>(
        p_y, p_cpi, out, T_LEN, D_MODEL, D_MODEL);
}